// round 7
// baseline (speedup 1.0000x reference)
#include <cstdint>
#include <cuda_runtime.h>
#include <cuda_bf16.h>
#include <mma.h>

using namespace nvcuda;

// Problem constants
#define Mrows 16384
#define QKV_N 3072
#define Dn 1024

// Scratch (device globals: allocation-free)
__device__ float g_qkv[(size_t)Mrows * QKV_N];    // 192 MB
__device__ float g_attn[(size_t)Mrows * Dn];      // 64 MB
__device__ float g_xr[(size_t)Mrows * Dn];        // 64 MB  (tf32-rounded x)
__device__ float g_wqkvr[(size_t)Dn * QKV_N];     // 12 MB  (tf32-rounded Wqkv)
__device__ float g_woutr[(size_t)Dn * Dn];        // 4 MB   (tf32-rounded Wout)

__device__ __forceinline__ float round_tf32(float x) {
    unsigned u;
    asm("cvt.rn.tf32.f32 %0, %1;" : "=r"(u) : "f"(x));
    return __uint_as_float(u);
}

__device__ __forceinline__ void cp_async16(float* smem_dst, const float* gmem_src) {
    unsigned s = (unsigned)__cvta_generic_to_shared(smem_dst);
    asm volatile("cp.async.cg.shared.global [%0], [%1], 16;\n" :: "r"(s), "l"(gmem_src));
}
__device__ __forceinline__ void cp_commit() {
    asm volatile("cp.async.commit_group;\n" ::);
}
template<int N>
__device__ __forceinline__ void cp_wait() {
    asm volatile("cp.async.wait_group %0;\n" :: "n"(N));
}

// ---------------------------------------------------------------------------
// TF32 WMMA GEMM, 3-stage cp.async pipeline.
// Block tile 128x128, 8 warps (2x4), warp tile 64x32, 256 threads.
// __launch_bounds__(256,2) forces <=128 regs -> 2 CTAs/SM = 16 warps/SM.
// Inputs MUST be pre-rounded to tf32 (no in-loop cvt).
// ---------------------------------------------------------------------------
#define BM 128
#define BN 128
#define BK 32
#define STAGES 3
#define A_LD (BK + 4)            // 36 floats
#define B_LD (BN + 4)            // 132 floats
#define A_STAGE (BM * A_LD)      // 4608 floats
#define B_STAGE (BK * B_LD)      // 4224 floats
#define SMEM_FLOATS (STAGES * (A_STAGE + B_STAGE))
#define SMEM_BYTES (SMEM_FLOATS * 4)   // 105984 bytes (x2 CTAs = 212KB < 228KB)

__global__ __launch_bounds__(256, 2)
void gemm_tf32_pipe_kernel(const float* __restrict__ A,
                           const float* __restrict__ B,
                           float* __restrict__ C,
                           int M, int N, int K)
{
    extern __shared__ float smem[];
    float* As = smem;                         // [STAGES][BM][A_LD]
    float* Bs = smem + STAGES * A_STAGE;      // [STAGES][BK][B_LD]

    const int tid = threadIdx.x;
    const int warpId = tid >> 5;
    const int warpRow = warpId >> 2;      // 0..1  (64 rows each)
    const int warpCol = warpId & 3;       // 0..3  (32 cols each)

    const int rowBase = blockIdx.y * BM;
    const int colBase = blockIdx.x * BN;

    const int KT = K / BK;

    auto load_stage = [&](int kt, int stage) {
        const float* Ag = A + (size_t)rowBase * K + kt * BK;
        const float* Bg = B + (size_t)(kt * BK) * N + colBase;
        float* Asm = As + stage * A_STAGE;
        float* Bsm = Bs + stage * B_STAGE;
        // A tile: 128x32 floats = 1024 float4, 4 per thread
        #pragma unroll
        for (int i = 0; i < 4; i++) {
            int l = tid + i * 256;
            int ar = l >> 3, ac = (l & 7) << 2;
            cp_async16(Asm + ar * A_LD + ac, Ag + (size_t)ar * K + ac);
        }
        // B tile: 32x128 floats = 1024 float4, 4 per thread
        #pragma unroll
        for (int i = 0; i < 4; i++) {
            int l = tid + i * 256;
            int br = l >> 5, bc = (l & 31) << 2;
            cp_async16(Bsm + br * B_LD + bc, Bg + (size_t)br * N + bc);
        }
        cp_commit();
    };

    // Prefetch first STAGES-1 stages
    #pragma unroll
    for (int s = 0; s < STAGES - 1; s++)
        load_stage(s, s);

    wmma::fragment<wmma::accumulator, 16, 16, 8, float> acc[4][2];
    #pragma unroll
    for (int m = 0; m < 4; m++)
        #pragma unroll
        for (int n = 0; n < 2; n++)
            wmma::fill_fragment(acc[m][n], 0.0f);

    for (int kt = 0; kt < KT; kt++) {
        cp_wait<STAGES - 2>();
        __syncthreads();

        // Issue loads for the stage STAGES-1 ahead (overlaps with compute)
        if (kt + STAGES - 1 < KT)
            load_stage(kt + STAGES - 1, (kt + STAGES - 1) % STAGES);

        const float* Asm = As + (kt % STAGES) * A_STAGE;
        const float* Bsm = Bs + (kt % STAGES) * B_STAGE;

        #pragma unroll
        for (int kk = 0; kk < BK / 8; kk++) {
            wmma::fragment<wmma::matrix_a, 16, 16, 8, wmma::precision::tf32, wmma::row_major> af[4];
            wmma::fragment<wmma::matrix_b, 16, 16, 8, wmma::precision::tf32, wmma::row_major> bf[2];
            #pragma unroll
            for (int m = 0; m < 4; m++)
                wmma::load_matrix_sync(af[m], Asm + (warpRow * 64 + m * 16) * A_LD + kk * 8, A_LD);
            #pragma unroll
            for (int n = 0; n < 2; n++)
                wmma::load_matrix_sync(bf[n], Bsm + (kk * 8) * B_LD + warpCol * 32 + n * 16, B_LD);
            #pragma unroll
            for (int m = 0; m < 4; m++)
                #pragma unroll
                for (int n = 0; n < 2; n++)
                    wmma::mma_sync(acc[m][n], af[m], bf[n], acc[m][n]);
        }
        __syncthreads();
    }

    // Epilogue: direct global store
    #pragma unroll
    for (int m = 0; m < 4; m++) {
        #pragma unroll
        for (int n = 0; n < 2; n++) {
            int r = rowBase + warpRow * 64 + m * 16;
            int c = colBase + warpCol * 32 + n * 16;
            wmma::store_matrix_sync(C + (size_t)r * N + c, acc[m][n], N, wmma::mem_row_major);
        }
    }
}

// ---------------------------------------------------------------------------
// Elementwise tf32 RN rounding (pre-round GEMM operands)
// ---------------------------------------------------------------------------
__global__ void round_tf32_kernel(const float4* __restrict__ in,
                                  float4* __restrict__ out, int n4)
{
    int i = blockIdx.x * blockDim.x + threadIdx.x;
    if (i < n4) {
        float4 v = in[i];
        v.x = round_tf32(v.x); v.y = round_tf32(v.y);
        v.z = round_tf32(v.z); v.w = round_tf32(v.w);
        out[i] = v;
    }
}

// ---------------------------------------------------------------------------
// Per-token head-attention: one block per token. Output tf32-rounded
// (feeds GEMM2 without in-loop conversion).
// ---------------------------------------------------------------------------
__global__ __launch_bounds__(256, 8)
void attn_kernel(const float* __restrict__ qkv, float* __restrict__ out)
{
    __shared__ float sq[16 * 64];
    __shared__ float sk[16 * 65];
    __shared__ float sv[16 * 64];
    __shared__ float sattn[16 * 16];

    const int t = blockIdx.x;
    const float* base = qkv + (size_t)t * QKV_N;
    const int tid = threadIdx.x;

    #pragma unroll
    for (int idx = tid; idx < 1024; idx += 256) {
        int r = idx >> 6, d = idx & 63;
        sq[idx]        = base[idx];
        sk[r * 65 + d] = base[1024 + idx];
        sv[idx]        = base[2048 + idx];
    }
    __syncthreads();

    const int i = tid >> 4, j = tid & 15;
    float s = 0.0f;
    #pragma unroll
    for (int d = 0; d < 64; d++)
        s += sq[i * 64 + d] * sk[j * 65 + d];
    s *= 0.125f;

    float mx = s;
    #pragma unroll
    for (int off = 8; off; off >>= 1)
        mx = fmaxf(mx, __shfl_xor_sync(0xffffffffu, mx, off));
    float e = __expf(s - mx);
    float sum = e;
    #pragma unroll
    for (int off = 8; off; off >>= 1)
        sum += __shfl_xor_sync(0xffffffffu, sum, off);
    sattn[i * 16 + j] = e / sum;
    __syncthreads();

    #pragma unroll
    for (int idx = tid; idx < 1024; idx += 256) {
        int oi = idx >> 6, od = idx & 63;
        float acc = 0.0f;
        #pragma unroll
        for (int jj = 0; jj < 16; jj++)
            acc += sattn[oi * 16 + jj] * sv[jj * 64 + od];
        out[(size_t)t * Dn + idx] = round_tf32(acc);
    }
}

// ---------------------------------------------------------------------------
extern "C" void kernel_launch(void* const* d_in, const int* in_sizes, int n_in,
                              void* d_out, int out_size)
{
    const float* x    = (const float*)d_in[0];
    const float* Wqkv = (const float*)d_in[1];
    const float* Wout = (const float*)d_in[2];
    float* out = (float*)d_out;

    float *qkv_p, *attn_p, *xr_p, *wqkvr_p, *woutr_p;
    cudaGetSymbolAddress((void**)&qkv_p, g_qkv);
    cudaGetSymbolAddress((void**)&attn_p, g_attn);
    cudaGetSymbolAddress((void**)&xr_p, g_xr);
    cudaGetSymbolAddress((void**)&wqkvr_p, g_wqkvr);
    cudaGetSymbolAddress((void**)&woutr_p, g_woutr);

    static bool attr_set = false;
    if (!attr_set) {
        cudaFuncSetAttribute(gemm_tf32_pipe_kernel,
                             cudaFuncAttributeMaxDynamicSharedMemorySize, SMEM_BYTES);
        attr_set = true;
    }

    // Pre-round operands to tf32 (RN) once.
    {
        int n4x = (Mrows * Dn) / 4;
        round_tf32_kernel<<<(n4x + 255) / 256, 256>>>((const float4*)x, (float4*)xr_p, n4x);
        int n4q = (Dn * QKV_N) / 4;
        round_tf32_kernel<<<(n4q + 255) / 256, 256>>>((const float4*)Wqkv, (float4*)wqkvr_p, n4q);
        int n4o = (Dn * Dn) / 4;
        round_tf32_kernel<<<(n4o + 255) / 256, 256>>>((const float4*)Wout, (float4*)woutr_p, n4o);
    }

    // GEMM1: qkv = x @ Wqkv   (16384 x 3072, K=1024)
    {
        dim3 grid(QKV_N / BN, Mrows / BM);
        gemm_tf32_pipe_kernel<<<grid, 256, SMEM_BYTES>>>(xr_p, wqkvr_p, qkv_p,
                                                         Mrows, QKV_N, Dn);
    }

    // Attention per token
    attn_kernel<<<Mrows, 256>>>(qkv_p, attn_p);

    // GEMM2: out = attn @ Wout  (16384 x 1024, K=1024)
    {
        dim3 grid(Dn / BN, Mrows / BM);
        gemm_tf32_pipe_kernel<<<grid, 256, SMEM_BYTES>>>(attn_p, woutr_p, out,
                                                         Mrows, Dn, Dn);
    }
}

// round 8
// speedup vs baseline: 1.1995x; 1.1995x over previous
#include <cstdint>
#include <cuda_runtime.h>
#include <cuda_bf16.h>
#include <mma.h>

using namespace nvcuda;

// Problem constants
#define Mrows 16384
#define QKV_N 3072
#define Dn 1024

// Scratch (device globals: allocation-free)
__device__ float g_qkv[(size_t)Mrows * QKV_N];    // 192 MB
__device__ float g_attn[(size_t)Mrows * Dn];      // 64 MB
__device__ float g_xr[(size_t)Mrows * Dn];        // 64 MB  (tf32-rounded x)
__device__ float g_wqkvr[(size_t)Dn * QKV_N];     // 12 MB  (tf32-rounded Wqkv)
__device__ float g_woutr[(size_t)Dn * Dn];        // 4 MB   (tf32-rounded Wout)

__device__ __forceinline__ float round_tf32(float x) {
    unsigned u;
    asm("cvt.rn.tf32.f32 %0, %1;" : "=r"(u) : "f"(x));
    return __uint_as_float(u);
}

__device__ __forceinline__ void cp_async16(float* smem_dst, const float* gmem_src) {
    unsigned s = (unsigned)__cvta_generic_to_shared(smem_dst);
    asm volatile("cp.async.cg.shared.global [%0], [%1], 16;\n" :: "r"(s), "l"(gmem_src));
}
__device__ __forceinline__ void cp_commit() {
    asm volatile("cp.async.commit_group;\n" ::);
}
template<int N>
__device__ __forceinline__ void cp_wait() {
    asm volatile("cp.async.wait_group %0;\n" :: "n"(N));
}

// ---------------------------------------------------------------------------
// TF32 WMMA GEMM, 3-stage cp.async pipeline.
// Block tile 128x128, 4 warps (2x2), warp tile 64x64, 128 threads,
// 2 CTAs/SM. One barrier per K-tile; load issue interleaved with MMA.
// Inputs MUST be pre-rounded to tf32 (no in-loop cvt).
// ---------------------------------------------------------------------------
#define BM 128
#define BN 128
#define BK 32
#define STAGES 3
#define A_LD (BK + 4)            // 36 floats
#define B_LD (BN + 4)            // 132 floats
#define A_STAGE (BM * A_LD)      // 4608 floats
#define B_STAGE (BK * B_LD)      // 4224 floats
#define SMEM_FLOATS (STAGES * (A_STAGE + B_STAGE))
#define SMEM_BYTES (SMEM_FLOATS * 4)   // 105984 bytes (x2 CTAs = 207KB < 228KB)

__global__ __launch_bounds__(128, 2)
void gemm_tf32_pipe_kernel(const float* __restrict__ A,
                           const float* __restrict__ B,
                           float* __restrict__ C,
                           int M, int N, int K)
{
    extern __shared__ float smem[];
    float* As = smem;                         // [STAGES][BM][A_LD]
    float* Bs = smem + STAGES * A_STAGE;      // [STAGES][BK][B_LD]

    const int tid = threadIdx.x;
    const int warpId = tid >> 5;
    const int warpRow = warpId >> 1;      // 0..1  (64 rows each)
    const int warpCol = warpId & 1;       // 0..1  (64 cols each)

    const int rowBase = blockIdx.y * BM;
    const int colBase = blockIdx.x * BN;

    const int KT = K / BK;

    // Full-stage load (prologue only)
    auto load_stage_full = [&](int kt, int stage) {
        const float* Ag = A + (size_t)rowBase * K + kt * BK;
        const float* Bg = B + (size_t)(kt * BK) * N + colBase;
        float* Asm = As + stage * A_STAGE;
        float* Bsm = Bs + stage * B_STAGE;
        #pragma unroll
        for (int i = 0; i < 8; i++) {
            int l = tid + i * 128;
            int ar = l >> 3, ac = (l & 7) << 2;
            cp_async16(Asm + ar * A_LD + ac, Ag + (size_t)ar * K + ac);
        }
        #pragma unroll
        for (int i = 0; i < 8; i++) {
            int l = tid + i * 128;
            int br = l >> 5, bc = (l & 31) << 2;
            cp_async16(Bsm + br * B_LD + bc, Bg + (size_t)br * N + bc);
        }
        cp_commit();
    };

    // Quarter-stage loads (interleaved into the kk loop):
    // part 0/1: A halves, part 2/3: B halves.
    auto load_stage_part = [&](int kt, int stage, int part) {
        float* Asm = As + stage * A_STAGE;
        float* Bsm = Bs + stage * B_STAGE;
        if (part < 2) {
            const float* Ag = A + (size_t)rowBase * K + kt * BK;
            #pragma unroll
            for (int i = 0; i < 4; i++) {
                int l = tid + (part * 4 + i) * 128;
                int ar = l >> 3, ac = (l & 7) << 2;
                cp_async16(Asm + ar * A_LD + ac, Ag + (size_t)ar * K + ac);
            }
        } else {
            const float* Bg = B + (size_t)(kt * BK) * N + colBase;
            #pragma unroll
            for (int i = 0; i < 4; i++) {
                int l = tid + ((part - 2) * 4 + i) * 128;
                int br = l >> 5, bc = (l & 31) << 2;
                cp_async16(Bsm + br * B_LD + bc, Bg + (size_t)br * N + bc);
            }
        }
    };

    // Prologue: prefetch stages 0,1
    load_stage_full(0, 0);
    load_stage_full(1, 1);

    wmma::fragment<wmma::accumulator, 16, 16, 8, float> acc[4][4];
    #pragma unroll
    for (int m = 0; m < 4; m++)
        #pragma unroll
        for (int n = 0; n < 4; n++)
            wmma::fill_fragment(acc[m][n], 0.0f);

    for (int kt = 0; kt < KT; kt++) {
        cp_wait<STAGES - 2>();
        __syncthreads();   // single barrier per K-tile (bottom one is redundant:
                           // loads below target buf (kt+2)%3 == (kt-1)%3, whose last
                           // reader finished before this barrier)

        const bool doLoad = (kt + STAGES - 1 < KT);
        const int  ldStage = (kt + STAGES - 1) % STAGES;

        const float* Asm = As + (kt % STAGES) * A_STAGE;
        const float* Bsm = Bs + (kt % STAGES) * B_STAGE;

        #pragma unroll
        for (int kk = 0; kk < BK / 8; kk++) {
            wmma::fragment<wmma::matrix_a, 16, 16, 8, wmma::precision::tf32, wmma::row_major> af[4];
            wmma::fragment<wmma::matrix_b, 16, 16, 8, wmma::precision::tf32, wmma::row_major> bf[4];
            #pragma unroll
            for (int m = 0; m < 4; m++)
                wmma::load_matrix_sync(af[m], Asm + (warpRow * 64 + m * 16) * A_LD + kk * 8, A_LD);
            #pragma unroll
            for (int n = 0; n < 4; n++)
                wmma::load_matrix_sync(bf[n], Bsm + (kk * 8) * B_LD + warpCol * 64 + n * 16, B_LD);

            // Interleave a quarter of the next-stage loads with each kk step
            if (doLoad)
                load_stage_part(kt + STAGES - 1, ldStage, kk);

            #pragma unroll
            for (int m = 0; m < 4; m++)
                #pragma unroll
                for (int n = 0; n < 4; n++)
                    wmma::mma_sync(acc[m][n], af[m], bf[n], acc[m][n]);
        }
        cp_commit();   // real or empty — keeps wait_group accounting uniform
    }

    // Epilogue: direct global store
    #pragma unroll
    for (int m = 0; m < 4; m++) {
        #pragma unroll
        for (int n = 0; n < 4; n++) {
            int r = rowBase + warpRow * 64 + m * 16;
            int c = colBase + warpCol * 64 + n * 16;
            wmma::store_matrix_sync(C + (size_t)r * N + c, acc[m][n], N, wmma::mem_row_major);
        }
    }
}

// ---------------------------------------------------------------------------
// Elementwise tf32 RN rounding (pre-round GEMM operands)
// ---------------------------------------------------------------------------
__global__ void round_tf32_kernel(const float4* __restrict__ in,
                                  float4* __restrict__ out, int n4)
{
    int i = blockIdx.x * blockDim.x + threadIdx.x;
    if (i < n4) {
        float4 v = in[i];
        v.x = round_tf32(v.x); v.y = round_tf32(v.y);
        v.z = round_tf32(v.z); v.w = round_tf32(v.w);
        out[i] = v;
    }
}

// ---------------------------------------------------------------------------
// Per-token head-attention: one block per token. Output tf32-rounded
// (feeds GEMM2 without in-loop conversion).
// ---------------------------------------------------------------------------
__global__ __launch_bounds__(256, 8)
void attn_kernel(const float* __restrict__ qkv, float* __restrict__ out)
{
    __shared__ float sq[16 * 64];
    __shared__ float sk[16 * 65];
    __shared__ float sv[16 * 64];
    __shared__ float sattn[16 * 16];

    const int t = blockIdx.x;
    const float* base = qkv + (size_t)t * QKV_N;
    const int tid = threadIdx.x;

    #pragma unroll
    for (int idx = tid; idx < 1024; idx += 256) {
        int r = idx >> 6, d = idx & 63;
        sq[idx]        = base[idx];
        sk[r * 65 + d] = base[1024 + idx];
        sv[idx]        = base[2048 + idx];
    }
    __syncthreads();

    const int i = tid >> 4, j = tid & 15;
    float s = 0.0f;
    #pragma unroll
    for (int d = 0; d < 64; d++)
        s += sq[i * 64 + d] * sk[j * 65 + d];
    s *= 0.125f;

    float mx = s;
    #pragma unroll
    for (int off = 8; off; off >>= 1)
        mx = fmaxf(mx, __shfl_xor_sync(0xffffffffu, mx, off));
    float e = __expf(s - mx);
    float sum = e;
    #pragma unroll
    for (int off = 8; off; off >>= 1)
        sum += __shfl_xor_sync(0xffffffffu, sum, off);
    sattn[i * 16 + j] = e / sum;
    __syncthreads();

    #pragma unroll
    for (int idx = tid; idx < 1024; idx += 256) {
        int oi = idx >> 6, od = idx & 63;
        float acc = 0.0f;
        #pragma unroll
        for (int jj = 0; jj < 16; jj++)
            acc += sattn[oi * 16 + jj] * sv[jj * 64 + od];
        out[(size_t)t * Dn + idx] = round_tf32(acc);
    }
}

// ---------------------------------------------------------------------------
extern "C" void kernel_launch(void* const* d_in, const int* in_sizes, int n_in,
                              void* d_out, int out_size)
{
    const float* x    = (const float*)d_in[0];
    const float* Wqkv = (const float*)d_in[1];
    const float* Wout = (const float*)d_in[2];
    float* out = (float*)d_out;

    float *qkv_p, *attn_p, *xr_p, *wqkvr_p, *woutr_p;
    cudaGetSymbolAddress((void**)&qkv_p, g_qkv);
    cudaGetSymbolAddress((void**)&attn_p, g_attn);
    cudaGetSymbolAddress((void**)&xr_p, g_xr);
    cudaGetSymbolAddress((void**)&wqkvr_p, g_wqkvr);
    cudaGetSymbolAddress((void**)&woutr_p, g_woutr);

    static bool attr_set = false;
    if (!attr_set) {
        cudaFuncSetAttribute(gemm_tf32_pipe_kernel,
                             cudaFuncAttributeMaxDynamicSharedMemorySize, SMEM_BYTES);
        attr_set = true;
    }

    // Pre-round operands to tf32 (RN) once.
    {
        int n4x = (Mrows * Dn) / 4;
        round_tf32_kernel<<<(n4x + 255) / 256, 256>>>((const float4*)x, (float4*)xr_p, n4x);
        int n4q = (Dn * QKV_N) / 4;
        round_tf32_kernel<<<(n4q + 255) / 256, 256>>>((const float4*)Wqkv, (float4*)wqkvr_p, n4q);
        int n4o = (Dn * Dn) / 4;
        round_tf32_kernel<<<(n4o + 255) / 256, 256>>>((const float4*)Wout, (float4*)woutr_p, n4o);
    }

    // GEMM1: qkv = x @ Wqkv   (16384 x 3072, K=1024)
    {
        dim3 grid(QKV_N / BN, Mrows / BM);
        gemm_tf32_pipe_kernel<<<grid, 128, SMEM_BYTES>>>(xr_p, wqkvr_p, qkv_p,
                                                         Mrows, QKV_N, Dn);
    }

    // Attention per token
    attn_kernel<<<Mrows, 256>>>(qkv_p, attn_p);

    // GEMM2: out = attn @ Wout  (16384 x 1024, K=1024)
    {
        dim3 grid(Dn / BN, Mrows / BM);
        gemm_tf32_pipe_kernel<<<grid, 128, SMEM_BYTES>>>(attn_p, woutr_p, out,
                                                         Mrows, Dn, Dn);
    }
}

// round 9
// speedup vs baseline: 3.9958x; 3.3311x over previous
#include <cstdint>
#include <cuda_runtime.h>
#include <cuda_fp16.h>
#include <mma.h>

using namespace nvcuda;

// Problem constants
#define Mrows 16384
#define QKV_N 3072
#define Dn 1024

// Scratch (device globals: allocation-free)
__device__ float  g_qkv[(size_t)Mrows * QKV_N];    // 192 MB (fp32 qkv for attention)
__device__ __half g_attnh[(size_t)Mrows * Dn];     // 32 MB  (fp16 attention out)
__device__ __half g_xh[(size_t)Mrows * Dn];        // 32 MB  (fp16 x)
__device__ __half g_wqkvh[(size_t)Dn * QKV_N];     // 6 MB   (fp16 Wqkv)
__device__ __half g_wouth[(size_t)Dn * Dn];        // 2 MB   (fp16 Wout)

__device__ __forceinline__ void cp_async16(__half* smem_dst, const __half* gmem_src) {
    unsigned s = (unsigned)__cvta_generic_to_shared(smem_dst);
    asm volatile("cp.async.cg.shared.global [%0], [%1], 16;\n" :: "r"(s), "l"(gmem_src));
}
__device__ __forceinline__ void cp_commit() {
    asm volatile("cp.async.commit_group;\n" ::);
}
template<int N>
__device__ __forceinline__ void cp_wait() {
    asm volatile("cp.async.wait_group %0;\n" :: "n"(N));
}

// ---------------------------------------------------------------------------
// FP16 WMMA GEMM (fp32 accumulate), 3-stage cp.async pipeline.
// Block tile 128x128, BK=64, 4 warps (2x2), warp tile 64x64, 128 threads,
// 2 CTAs/SM. One barrier per K-tile; load issue interleaved with MMA.
// ---------------------------------------------------------------------------
#define BM 128
#define BN 128
#define BK 64
#define STAGES 3
#define A_LD (BK + 8)            // 72 halves (144B, mult of 16B)
#define B_LD (BN + 8)            // 136 halves (272B, mult of 16B)
#define A_STAGE (BM * A_LD)      // 9216 halves
#define B_STAGE (BK * B_LD)      // 8704 halves
#define SMEM_HALVES (STAGES * (A_STAGE + B_STAGE))
#define SMEM_BYTES (SMEM_HALVES * 2)   // 107520 B (x2 CTAs = 215KB < 228KB)

__global__ __launch_bounds__(128, 2)
void gemm_fp16_pipe_kernel(const __half* __restrict__ A,
                           const __half* __restrict__ B,
                           float* __restrict__ C,
                           int M, int N, int K)
{
    extern __shared__ __half smem[];
    __half* As = smem;                         // [STAGES][BM][A_LD]
    __half* Bs = smem + STAGES * A_STAGE;      // [STAGES][BK][B_LD]

    const int tid = threadIdx.x;
    const int warpId = tid >> 5;
    const int warpRow = warpId >> 1;      // 0..1  (64 rows each)
    const int warpCol = warpId & 1;       // 0..1  (64 cols each)

    const int rowBase = blockIdx.y * BM;
    const int colBase = blockIdx.x * BN;

    const int KT = K / BK;

    // Full-stage load (prologue only).
    // A tile: 128 rows x 64 halves = 1024 x 16B chunks; 8 per thread.
    // B tile:  64 rows x 128 halves = 1024 x 16B chunks; 8 per thread.
    auto load_stage_full = [&](int kt, int stage) {
        const __half* Ag = A + (size_t)rowBase * K + kt * BK;
        const __half* Bg = B + (size_t)(kt * BK) * N + colBase;
        __half* Asm = As + stage * A_STAGE;
        __half* Bsm = Bs + stage * B_STAGE;
        #pragma unroll
        for (int i = 0; i < 8; i++) {
            int l = tid + i * 128;
            int ar = l >> 3, ac = (l & 7) << 3;
            cp_async16(Asm + ar * A_LD + ac, Ag + (size_t)ar * K + ac);
        }
        #pragma unroll
        for (int i = 0; i < 8; i++) {
            int l = tid + i * 128;
            int br = l >> 4, bc = (l & 15) << 3;
            cp_async16(Bsm + br * B_LD + bc, Bg + (size_t)br * N + bc);
        }
        cp_commit();
    };

    // Quarter-stage loads interleaved into the kk loop:
    // part 0/1: A halves, part 2/3: B halves (4 chunks each).
    auto load_stage_part = [&](int kt, int stage, int part) {
        __half* Asm = As + stage * A_STAGE;
        __half* Bsm = Bs + stage * B_STAGE;
        if (part < 2) {
            const __half* Ag = A + (size_t)rowBase * K + kt * BK;
            #pragma unroll
            for (int i = 0; i < 4; i++) {
                int l = tid + (part * 4 + i) * 128;
                int ar = l >> 3, ac = (l & 7) << 3;
                cp_async16(Asm + ar * A_LD + ac, Ag + (size_t)ar * K + ac);
            }
        } else {
            const __half* Bg = B + (size_t)(kt * BK) * N + colBase;
            #pragma unroll
            for (int i = 0; i < 4; i++) {
                int l = tid + ((part - 2) * 4 + i) * 128;
                int br = l >> 4, bc = (l & 15) << 3;
                cp_async16(Bsm + br * B_LD + bc, Bg + (size_t)br * N + bc);
            }
        }
    };

    // Prologue: prefetch stages 0,1
    load_stage_full(0, 0);
    load_stage_full(1, 1);

    wmma::fragment<wmma::accumulator, 16, 16, 16, float> acc[4][4];
    #pragma unroll
    for (int m = 0; m < 4; m++)
        #pragma unroll
        for (int n = 0; n < 4; n++)
            wmma::fill_fragment(acc[m][n], 0.0f);

    for (int kt = 0; kt < KT; kt++) {
        cp_wait<STAGES - 2>();
        __syncthreads();   // single barrier per K-tile (bottom barrier is redundant)

        const bool doLoad = (kt + STAGES - 1 < KT);
        const int  ldStage = (kt + STAGES - 1) % STAGES;

        const __half* Asm = As + (kt % STAGES) * A_STAGE;
        const __half* Bsm = Bs + (kt % STAGES) * B_STAGE;

        #pragma unroll
        for (int kk = 0; kk < BK / 16; kk++) {
            wmma::fragment<wmma::matrix_a, 16, 16, 16, __half, wmma::row_major> af[4];
            wmma::fragment<wmma::matrix_b, 16, 16, 16, __half, wmma::row_major> bf[4];
            #pragma unroll
            for (int m = 0; m < 4; m++)
                wmma::load_matrix_sync(af[m], Asm + (warpRow * 64 + m * 16) * A_LD + kk * 16, A_LD);
            #pragma unroll
            for (int n = 0; n < 4; n++)
                wmma::load_matrix_sync(bf[n], Bsm + (kk * 16) * B_LD + warpCol * 64 + n * 16, B_LD);

            // Interleave a quarter of the next-stage loads with each kk step
            if (doLoad)
                load_stage_part(kt + STAGES - 1, ldStage, kk);

            #pragma unroll
            for (int m = 0; m < 4; m++)
                #pragma unroll
                for (int n = 0; n < 4; n++)
                    wmma::mma_sync(acc[m][n], af[m], bf[n], acc[m][n]);
        }
        cp_commit();   // real or empty — keeps wait_group accounting uniform
    }

    // Epilogue: direct global store (fp32)
    #pragma unroll
    for (int m = 0; m < 4; m++) {
        #pragma unroll
        for (int n = 0; n < 4; n++) {
            int r = rowBase + warpRow * 64 + m * 16;
            int c = colBase + warpCol * 64 + n * 16;
            wmma::store_matrix_sync(C + (size_t)r * N + c, acc[m][n], N, wmma::mem_row_major);
        }
    }
}

// ---------------------------------------------------------------------------
// Elementwise fp32 -> fp16 (RN) conversion
// ---------------------------------------------------------------------------
__global__ void f32_to_f16_kernel(const float4* __restrict__ in,
                                  __half2* __restrict__ out, int n4)
{
    int i = blockIdx.x * blockDim.x + threadIdx.x;
    if (i < n4) {
        float4 v = in[i];
        out[2 * i]     = __floats2half2_rn(v.x, v.y);
        out[2 * i + 1] = __floats2half2_rn(v.z, v.w);
    }
}

// ---------------------------------------------------------------------------
// Per-token head-attention: one block per token (fp32 math, fp16 output).
// ---------------------------------------------------------------------------
__global__ __launch_bounds__(256, 8)
void attn_kernel(const float* __restrict__ qkv, __half* __restrict__ out)
{
    __shared__ float sq[16 * 64];
    __shared__ float sk[16 * 65];
    __shared__ float sv[16 * 64];
    __shared__ float sattn[16 * 16];

    const int t = blockIdx.x;
    const float* base = qkv + (size_t)t * QKV_N;
    const int tid = threadIdx.x;

    #pragma unroll
    for (int idx = tid; idx < 1024; idx += 256) {
        int r = idx >> 6, d = idx & 63;
        sq[idx]        = base[idx];
        sk[r * 65 + d] = base[1024 + idx];
        sv[idx]        = base[2048 + idx];
    }
    __syncthreads();

    const int i = tid >> 4, j = tid & 15;
    float s = 0.0f;
    #pragma unroll
    for (int d = 0; d < 64; d++)
        s += sq[i * 64 + d] * sk[j * 65 + d];
    s *= 0.125f;

    float mx = s;
    #pragma unroll
    for (int off = 8; off; off >>= 1)
        mx = fmaxf(mx, __shfl_xor_sync(0xffffffffu, mx, off));
    float e = __expf(s - mx);
    float sum = e;
    #pragma unroll
    for (int off = 8; off; off >>= 1)
        sum += __shfl_xor_sync(0xffffffffu, sum, off);
    sattn[i * 16 + j] = e / sum;
    __syncthreads();

    #pragma unroll
    for (int idx = tid; idx < 1024; idx += 256) {
        int oi = idx >> 6, od = idx & 63;
        float acc = 0.0f;
        #pragma unroll
        for (int jj = 0; jj < 16; jj++)
            acc += sattn[oi * 16 + jj] * sv[jj * 64 + od];
        out[(size_t)t * Dn + idx] = __float2half_rn(acc);
    }
}

// ---------------------------------------------------------------------------
extern "C" void kernel_launch(void* const* d_in, const int* in_sizes, int n_in,
                              void* d_out, int out_size)
{
    const float* x    = (const float*)d_in[0];
    const float* Wqkv = (const float*)d_in[1];
    const float* Wout = (const float*)d_in[2];
    float* out = (float*)d_out;

    float *qkv_p;
    __half *attnh_p, *xh_p, *wqkvh_p, *wouth_p;
    cudaGetSymbolAddress((void**)&qkv_p, g_qkv);
    cudaGetSymbolAddress((void**)&attnh_p, g_attnh);
    cudaGetSymbolAddress((void**)&xh_p, g_xh);
    cudaGetSymbolAddress((void**)&wqkvh_p, g_wqkvh);
    cudaGetSymbolAddress((void**)&wouth_p, g_wouth);

    static bool attr_set = false;
    if (!attr_set) {
        cudaFuncSetAttribute(gemm_fp16_pipe_kernel,
                             cudaFuncAttributeMaxDynamicSharedMemorySize, SMEM_BYTES);
        attr_set = true;
    }

    // Convert operands to fp16 (RN) once.
    {
        int n4x = (Mrows * Dn) / 4;
        f32_to_f16_kernel<<<(n4x + 255) / 256, 256>>>((const float4*)x, (__half2*)xh_p, n4x);
        int n4q = (Dn * QKV_N) / 4;
        f32_to_f16_kernel<<<(n4q + 255) / 256, 256>>>((const float4*)Wqkv, (__half2*)wqkvh_p, n4q);
        int n4o = (Dn * Dn) / 4;
        f32_to_f16_kernel<<<(n4o + 255) / 256, 256>>>((const float4*)Wout, (__half2*)wouth_p, n4o);
    }

    // GEMM1: qkv = x @ Wqkv   (16384 x 3072, K=1024), fp32 out
    {
        dim3 grid(QKV_N / BN, Mrows / BM);
        gemm_fp16_pipe_kernel<<<grid, 128, SMEM_BYTES>>>(xh_p, wqkvh_p, qkv_p,
                                                         Mrows, QKV_N, Dn);
    }

    // Attention per token (fp32 math, fp16 out)
    attn_kernel<<<Mrows, 256>>>(qkv_p, attnh_p);

    // GEMM2: out = attn @ Wout  (16384 x 1024, K=1024), fp32 out
    {
        dim3 grid(Dn / BN, Mrows / BM);
        gemm_fp16_pipe_kernel<<<grid, 128, SMEM_BYTES>>>(attnh_p, wouth_p, out,
                                                         Mrows, Dn, Dn);
    }
}